// round 14
// baseline (speedup 1.0000x reference)
#include <cuda_runtime.h>
#include <cuda_bf16.h>

typedef unsigned long long u64;

// ---------------- f32x2 packed-math helpers (sm_103a FFMA2) ----------------
__device__ __forceinline__ u64 pack2(float lo, float hi) {
    u64 r;
    asm("mov.b64 %0, {%1, %2};" : "=l"(r)
        : "r"(__float_as_uint(lo)), "r"(__float_as_uint(hi)));
    return r;
}
__device__ __forceinline__ u64 bcast2(float v) { return pack2(v, v); }
__device__ __forceinline__ void fma2(u64& d, u64 a, u64 b) {
    asm("fma.rn.f32x2 %0, %1, %2, %0;" : "+l"(d) : "l"(a), "l"(b));
}
__device__ __forceinline__ float2 unpack2(u64 v) {
    unsigned lo, hi;
    asm("mov.b64 {%0, %1}, %2;" : "=r"(lo), "=r"(hi) : "l"(v));
    return make_float2(__uint_as_float(lo), __uint_as_float(hi));
}

// ---------------- scratch (allocation-free: __device__ globals) ----------------
__device__ float g_a1[64*32*63*63];
__device__ float g_a2[64*64*32*32];
__device__ float g_z [64*64*32*32];
__device__ float g_e [64*64*32*32];
__device__ float g_d1[64*64*64*64];
__device__ float g_d2[64*32*128*128];
__device__ double g_vq_loss;
__device__ double g_recon;

__global__ void k_zero() { g_vq_loss = 0.0; g_recon = 0.0; }

// ---------------- enc conv1: 3->32, k3 s2 p1, 125->63, relu (R8 form) -------
__global__ void __launch_bounds__(256) k_conv1(const float* __restrict__ x,
                                               const float* __restrict__ w,
                                               const float* __restrict__ b) {
    __shared__ u64 wp[3*9*8];
    int bid  = blockIdx.x;               // 1024 = 64n * 2cog * 8ib
    int ib   = bid & 7;
    int cog  = (bid >> 3) & 1;
    int n    = bid >> 4;
    int co0  = cog * 16;
    for (int i = threadIdx.x; i < 216; i += 256) {
        int jq = i & 7;
        int t  = (i >> 3) % 9;
        int ci = i / 72;
        int co = co0 + 2*jq;
        wp[(ci*9 + t)*8 + jq] = pack2(w[co*27 + ci*9 + t],
                                      w[(co+1)*27 + ci*9 + t]);
    }
    __syncthreads();
    int r2 = ib*256 + threadIdx.x;
    if (r2 >= 2016) return;
    int qp = r2 & 31;
    int oh = r2 >> 5;
    int ow0 = 2*qp;
    bool hasB = (qp != 31);
    u64 accA[8], accB[8];
    #pragma unroll
    for (int jq = 0; jq < 8; jq++) {
        u64 bv = pack2(b[co0+2*jq], b[co0+2*jq+1]);
        accA[jq] = bv; accB[jq] = bv;
    }
    const float* xb = x + n*3*125*125;
    int iwb = 4*qp - 1;
    #pragma unroll
    for (int ci = 0; ci < 3; ci++) {
        u64 col[3][5];
        #pragma unroll
        for (int kh = 0; kh < 3; kh++) {
            int ihh = 2*oh + kh - 1;
            bool hok = (unsigned)ihh < 125u;
            const float* row = xb + (ci*125 + ihh)*125;
            #pragma unroll
            for (int c = 0; c < 5; c++) {
                int iw = iwb + c;
                float v = (hok && (unsigned)iw < 125u) ? row[iw] : 0.f;
                col[kh][c] = bcast2(v);
            }
        }
        #pragma unroll
        for (int kh = 0; kh < 3; kh++) {
            #pragma unroll
            for (int kw = 0; kw < 3; kw++) {
                int t = kh*3 + kw;
                const ulonglong2* Wq = (const ulonglong2*)&wp[(ci*9 + t)*8];
                u64 cA = col[kh][kw];
                u64 cB = col[kh][kw+2];
                #pragma unroll
                for (int h = 0; h < 4; h++) {
                    ulonglong2 W = Wq[h];
                    fma2(accA[2*h],   W.x, cA);
                    fma2(accA[2*h+1], W.y, cA);
                    fma2(accB[2*h],   W.x, cB);
                    fma2(accB[2*h+1], W.y, cB);
                }
            }
        }
    }
    float* ob = g_a1 + ((n*32 + co0)*63 + oh)*63 + ow0;
    #pragma unroll
    for (int jq = 0; jq < 8; jq++) {
        float2 a = unpack2(accA[jq]);
        float2 c = unpack2(accB[jq]);
        float* o0 = ob + (2*jq)*3969;
        float* o1 = o0 + 3969;
        o0[0] = fmaxf(a.x, 0.f);
        o1[0] = fmaxf(a.y, 0.f);
        if (hasB) {
            o0[1] = fmaxf(c.x, 0.f);
            o1[1] = fmaxf(c.y, 0.f);
        }
    }
}

// ---------------- enc conv2: 32->64, k3 s2 p1, 63->32 (R8 form) ------
__global__ void __launch_bounds__(256) k_conv2(const float* __restrict__ w,
                                               const float* __restrict__ b) {
    __shared__ float2 wp[32][4][10];
    int bid   = blockIdx.x;              // 1024 = 64n * 8cog * 2ohhalf
    int ohh   = bid & 1;
    int cog   = (bid >> 1) & 7;
    int n     = bid >> 4;
    int co0   = cog * 8;
    for (int i = threadIdx.x; i < 32*4*9; i += 256) {
        int t  = i % 9;
        int jp = (i/9) & 3;
        int ci = i / 36;
        wp[ci][jp][t] = make_float2(w[((co0 + 2*jp)    *32 + ci)*9 + t],
                                    w[((co0 + 2*jp + 1)*32 + ci)*9 + t]);
    }
    __syncthreads();
    int q  = threadIdx.x & 15;
    int oh = ohh*16 + (threadIdx.x >> 4);
    u64 accA[4], accB[4];
    #pragma unroll
    for (int jp = 0; jp < 4; jp++) {
        u64 bv = pack2(b[co0+2*jp], b[co0+2*jp+1]);
        accA[jp] = bv; accB[jp] = bv;
    }
    const float* ib = g_a1 + n*32*63*63;
    int iwb = 4*q - 1;
    for (int ci = 0; ci < 32; ci++) {
        u64 col[3][5];
        #pragma unroll
        for (int kh = 0; kh < 3; kh++) {
            int ih = 2*oh + kh - 1;
            bool hok = (unsigned)ih < 63u;
            const float* row = ib + (ci*63 + ih)*63;
            #pragma unroll
            for (int c = 0; c < 5; c++) {
                int iw = iwb + c;
                float v = (hok && (unsigned)iw < 63u) ? row[iw] : 0.f;
                col[kh][c] = bcast2(v);
            }
        }
        #pragma unroll
        for (int jp = 0; jp < 4; jp++) {
            const ulonglong2* Wq = (const ulonglong2*)wp[ci][jp];
            ulonglong2 q0 = Wq[0];
            ulonglong2 q1 = Wq[1];
            ulonglong2 q2 = Wq[2];
            ulonglong2 q3 = Wq[3];
            u64 w8 = *(const u64*)&wp[ci][jp][8];
            fma2(accA[jp], q0.x, col[0][0]); fma2(accB[jp], q0.x, col[0][2]);
            fma2(accA[jp], q0.y, col[0][1]); fma2(accB[jp], q0.y, col[0][3]);
            fma2(accA[jp], q1.x, col[0][2]); fma2(accB[jp], q1.x, col[0][4]);
            fma2(accA[jp], q1.y, col[1][0]); fma2(accB[jp], q1.y, col[1][2]);
            fma2(accA[jp], q2.x, col[1][1]); fma2(accB[jp], q2.x, col[1][3]);
            fma2(accA[jp], q2.y, col[1][2]); fma2(accB[jp], q2.y, col[1][4]);
            fma2(accA[jp], q3.x, col[2][0]); fma2(accB[jp], q3.x, col[2][2]);
            fma2(accA[jp], q3.y, col[2][1]); fma2(accB[jp], q3.y, col[2][3]);
            fma2(accA[jp], w8,   col[2][2]); fma2(accB[jp], w8,   col[2][4]);
        }
    }
    int ohw = oh*32 + 2*q;
    #pragma unroll
    for (int jp = 0; jp < 4; jp++) {
        float2 a = unpack2(accA[jp]);
        float2 c = unpack2(accB[jp]);
        *(float2*)&g_a2[(n*64 + co0 + 2*jp    )*1024 + ohw]
            = make_float2(fmaxf(a.x,0.f), fmaxf(c.x,0.f));
        *(float2*)&g_a2[(n*64 + co0 + 2*jp + 1)*1024 + ohw]
            = make_float2(fmaxf(a.y,0.f), fmaxf(c.y,0.f));
    }
}

// ---------------- enc conv3: 64->64 1x1 (R1 scalar form) --------------------
__global__ void k_conv3(const float* __restrict__ w, const float* __restrict__ b) {
    __shared__ float ws[16*64];
    int bid  = blockIdx.x;                 // 1024 = 64n * 4cog * 4tile
    int tile = bid & 3;
    int cog  = (bid >> 2) & 3;
    int n    = bid >> 4;
    int co0  = cog * 16;
    for (int i = threadIdx.x; i < 1024; i += 256) ws[i] = w[co0*64 + i];
    __syncthreads();
    int hw = tile*256 + threadIdx.x;
    float acc[16];
    #pragma unroll
    for (int j = 0; j < 16; j++) acc[j] = b[co0 + j];
    const float* ib = g_a2 + n*64*1024;
    for (int ci = 0; ci < 64; ci++) {
        float v = ib[ci*1024 + hw];
        #pragma unroll
        for (int j = 0; j < 16; j++) acc[j] += ws[j*64 + ci] * v;
    }
    #pragma unroll
    for (int j = 0; j < 16; j++) g_z[(n*64 + co0 + j)*1024 + hw] = acc[j];
}

// ---------------- VQ: R8 math, grid 296 (2 CTAs per SM exactly) -------------
__global__ void __launch_bounds__(256) k_vq(const float* __restrict__ codebook) {
    __shared__ float4 cbs[128][16];
    __shared__ float  cns[128];
    __shared__ float  wsum[8];
    const int PXB = 222;                        // 296 * 222 = 65712 >= 65536
    int n  = blockIdx.x * PXB + threadIdx.x;
    bool act = (threadIdx.x < PXB) && (n < 65536);
    int bb = n >> 10;
    int hw = n & 1023;
    const float* zb = g_z + bb*65536 + hw;
    float zv[64];
    u64 zp[32];
    if (act) {
        #pragma unroll
        for (int d = 0; d < 64; d++) zv[d] = zb[d*1024];
        #pragma unroll
        for (int q = 0; q < 32; q++) zp[q] = pack2(zv[2*q], zv[2*q+1]);
    } else {
        #pragma unroll
        for (int d = 0; d < 64; d++) zv[d] = 0.f;
        #pragma unroll
        for (int q = 0; q < 32; q++) zp[q] = 0ull;
    }
    float best = 3.0e38f; int bidx = 0;
    for (int c = 0; c < 4; c++) {
        __syncthreads();
        const float4* src = (const float4*)(codebook + c*128*64);
        for (int i = threadIdx.x; i < 2048; i += 256)
            ((float4*)cbs)[i] = src[i];
        __syncthreads();
        if (threadIdx.x < 128) {
            const float* cc = (const float*)cbs[threadIdx.x];
            float s = 0.f;
            #pragma unroll
            for (int d = 0; d < 64; d++) s += cc[d]*cc[d];
            cns[threadIdx.x] = s;
        }
        __syncthreads();
        for (int k = 0; k < 128; k += 2) {
            const ulonglong2* ck0 = (const ulonglong2*)cbs[k];
            const ulonglong2* ck1 = (const ulonglong2*)cbs[k+1];
            u64 d0e = 0ull, d0o = 0ull, d1e = 0ull, d1o = 0ull;
            #pragma unroll
            for (int q2 = 0; q2 < 16; q2++) {
                ulonglong2 c0 = ck0[q2];
                ulonglong2 c1 = ck1[q2];
                fma2(d0e, c0.x, zp[2*q2]);
                fma2(d0o, c0.y, zp[2*q2+1]);
                fma2(d1e, c1.x, zp[2*q2]);
                fma2(d1o, c1.y, zp[2*q2+1]);
            }
            float2 a0 = unpack2(d0e), b0 = unpack2(d0o);
            float2 a1 = unpack2(d1e), b1 = unpack2(d1o);
            float dist0 = cns[k]   - 2.f*(a0.x + a0.y + b0.x + b0.y);
            float dist1 = cns[k+1] - 2.f*(a1.x + a1.y + b1.x + b1.y);
            if (dist0 < best) { best = dist0; bidx = c*128 + k; }
            if (dist1 < best) { best = dist1; bidx = c*128 + k + 1; }
        }
    }
    float ls = 0.f;
    if (act) {
        const float* cbest = codebook + bidx*64;
        float* eb = g_e + bb*65536 + hw;
        #pragma unroll
        for (int d = 0; d < 64; d++) {
            float qv = cbest[d];
            float df = qv - zv[d];
            ls += df*df;
            eb[d*1024] = qv;
        }
    }
    #pragma unroll
    for (int off = 16; off; off >>= 1) ls += __shfl_down_sync(0xffffffffu, ls, off);
    if ((threadIdx.x & 31) == 0) wsum[threadIdx.x >> 5] = ls;
    __syncthreads();
    if (threadIdx.x == 0) {
        float s = 0.f;
        #pragma unroll
        for (int i = 0; i < 8; i++) s += wsum[i];
        atomicAdd(&g_vq_loss, (double)s);
    }
}

// =====================================================================
// decT core (R8) + ci-loop unroll 2 for doubled LDG MLP
// =====================================================================
template<int S>
__device__ __forceinline__ void dec_core(
    const float* __restrict__ ib, const float* __restrict__ w, int CO,
    const float* __restrict__ b, float* __restrict__ ob,
    int co0, int m0, int l0)
{
    __shared__ float2 wp[64][4][10];
    int tid = threadIdx.x;
    for (int i = tid; i < 64*4*9; i += 256) {
        int t  = i % 9;
        int jp = (i/9) & 3;
        int ci = i / 36;
        wp[ci][jp][t] = make_float2(w[(ci*CO + co0 + 2*jp    )*9 + t],
                                    w[(ci*CO + co0 + 2*jp + 1)*9 + t]);
    }
    __syncthreads();

    int dl = tid & 15, dm = tid >> 4;
    int l  = l0 + dl;
    int mA = m0 + dm;
    int mB = mA + 16;
    u64 aA[4][4], aB[4][4];
    #pragma unroll
    for (int jp = 0; jp < 4; jp++) {
        u64 bv = pack2(b[co0+2*jp], b[co0+2*jp+1]);
        #pragma unroll
        for (int p = 0; p < 4; p++) { aA[jp][p] = bv; aB[jp][p] = bv; }
    }
    bool lok  = (l  + 1) < S;
    bool mAok = (mA + 1) < S;
    bool mBok = (mB + 1) < S;
    const float* pA0 = ib + mA*S + l;
    const float* pB0 = ib + mB*S + l;
    #pragma unroll 2
    for (int ci = 0; ci < 64; ci++) {
        const float* pA = pA0 + ci*S*S;
        const float* pB = pB0 + ci*S*S;
        u64 A00 = bcast2(pA[0]);
        u64 A01 = bcast2(lok ? pA[1] : 0.f);
        u64 A10 = bcast2(mAok ? pA[S] : 0.f);
        u64 A11 = bcast2((mAok && lok) ? pA[S+1] : 0.f);
        u64 B00 = bcast2(pB[0]);
        u64 B01 = bcast2(lok ? pB[1] : 0.f);
        u64 B10 = bcast2(mBok ? pB[S] : 0.f);
        u64 B11 = bcast2((mBok && lok) ? pB[S+1] : 0.f);
        #pragma unroll
        for (int jp = 0; jp < 4; jp++) {
            const ulonglong2* Wq = (const ulonglong2*)wp[ci][jp];
            ulonglong2 q0 = Wq[0];
            ulonglong2 q1 = Wq[1];
            ulonglong2 q2 = Wq[2];
            ulonglong2 q3 = Wq[3];
            u64 w8 = *(const u64*)&wp[ci][jp][8];
            fma2(aA[jp][0], q2.x, A00); fma2(aB[jp][0], q2.x, B00);
            fma2(aA[jp][1], q1.y, A01); fma2(aB[jp][1], q1.y, B01);
            fma2(aA[jp][1], q2.y, A00); fma2(aB[jp][1], q2.y, B00);
            fma2(aA[jp][2], q0.y, A10); fma2(aB[jp][2], q0.y, B10);
            fma2(aA[jp][2], q3.y, A00); fma2(aB[jp][2], q3.y, B00);
            fma2(aA[jp][3], q0.x, A11); fma2(aB[jp][3], q0.x, B11);
            fma2(aA[jp][3], q1.x, A10); fma2(aB[jp][3], q1.x, B10);
            fma2(aA[jp][3], q3.x, A01); fma2(aB[jp][3], q3.x, B01);
            fma2(aA[jp][3], w8,   A00); fma2(aB[jp][3], w8,   B00);
        }
    }
    const int O = 2*S;
    #pragma unroll
    for (int jp = 0; jp < 4; jp++) {
        float2 a0 = unpack2(aA[jp][0]);
        float2 a1 = unpack2(aA[jp][1]);
        float2 a2 = unpack2(aA[jp][2]);
        float2 a3 = unpack2(aA[jp][3]);
        float* o0 = ob + (2*jp)*O*O + (2*mA)*O + 2*l;
        float* o1 = o0 + O*O;
        *(float2*)(o0)     = make_float2(fmaxf(a0.x,0.f), fmaxf(a1.x,0.f));
        *(float2*)(o0 + O) = make_float2(fmaxf(a2.x,0.f), fmaxf(a3.x,0.f));
        *(float2*)(o1)     = make_float2(fmaxf(a0.y,0.f), fmaxf(a1.y,0.f));
        *(float2*)(o1 + O) = make_float2(fmaxf(a2.y,0.f), fmaxf(a3.y,0.f));
        float2 b0 = unpack2(aB[jp][0]);
        float2 b1 = unpack2(aB[jp][1]);
        float2 b2 = unpack2(aB[jp][2]);
        float2 b3 = unpack2(aB[jp][3]);
        float* q0p = ob + (2*jp)*O*O + (2*mB)*O + 2*l;
        float* q1p = q0p + O*O;
        *(float2*)(q0p)     = make_float2(fmaxf(b0.x,0.f), fmaxf(b1.x,0.f));
        *(float2*)(q0p + O) = make_float2(fmaxf(b2.x,0.f), fmaxf(b3.x,0.f));
        *(float2*)(q1p)     = make_float2(fmaxf(b0.y,0.f), fmaxf(b1.y,0.f));
        *(float2*)(q1p + O) = make_float2(fmaxf(b2.y,0.f), fmaxf(b3.y,0.f));
    }
}

// decT1: 64->64, 32x32 -> 64x64
__global__ void __launch_bounds__(256, 2) k_dec1(const float* __restrict__ w,
                                                 const float* __restrict__ b) {
    int bid   = blockIdx.x;            // 1024 = 64n * 8cog * 2lhalf
    int lhalf = bid & 1;
    int cog   = (bid >> 1) & 7;
    int n     = bid >> 4;
    int co0   = cog * 8;
    dec_core<32>(g_e + n*64*1024, w, 64, b, g_d1 + (n*64 + co0)*4096,
                 co0, 0, lhalf*16);
}

// decT2: 64->32, 64x64 -> 128x128
__global__ void __launch_bounds__(256, 2) k_dec2(const float* __restrict__ w,
                                                 const float* __restrict__ b) {
    int bid  = blockIdx.x;             // 2048 = 64n * 4cog * 8tile
    int t    = bid & 7;
    int l0   = (t & 3) * 16;
    int m0   = (t >> 2) * 32;
    int cog  = (bid >> 3) & 3;
    int n    = bid >> 5;
    int co0  = cog * 8;
    dec_core<64>(g_d1 + n*64*4096, w, 32, b, g_d2 + (n*32 + co0)*16384,
                 co0, m0, l0);
}

// ---------------- decT3: 32->3, k2 s1 p2, 128->125 + recon loss (R8) --------
__global__ void k_dec3(const float* __restrict__ w, const float* __restrict__ bs,
                       const float* __restrict__ x, float* __restrict__ out) {
    __shared__ float ws[384];
    __shared__ float wsum[8];
    for (int i = threadIdx.x; i < 384; i += 256) ws[i] = w[i];
    __syncthreads();
    int idx = blockIdx.x * 256 + threadIdx.x;
    float lsum = 0.f;
    if (idx < 1000000) {
        int ow = idx % 125; int t = idx / 125;
        int oh = t % 125;   int n = t / 125;
        u64 accA[3], accB[3];
        #pragma unroll
        for (int co = 0; co < 3; co++) { accA[co] = 0ull; accB[co] = 0ull; }
        const float* ib = g_d2 + n*32*16384;
        const float* p  = ib + (oh+1)*128 + (ow+1);
        for (int ci = 0; ci < 32; ci++) {
            const float* q = p + ci*16384;
            u64 A = pack2(q[129], q[128]);
            u64 B = pack2(q[1],   q[0]);
            const ulonglong2* Wq = (const ulonglong2*)(ws + ci*12);
            ulonglong2 v0 = Wq[0];
            ulonglong2 v1 = Wq[1];
            ulonglong2 v2 = Wq[2];
            fma2(accA[0], v0.x, A); fma2(accB[0], v0.y, B);
            fma2(accA[1], v1.x, A); fma2(accB[1], v1.y, B);
            fma2(accA[2], v2.x, A); fma2(accB[2], v2.y, B);
        }
        #pragma unroll
        for (int co = 0; co < 3; co++) {
            float2 a = unpack2(accA[co]);
            float2 c = unpack2(accB[co]);
            float v = bs[co] + a.x + a.y + c.x + c.y;
            int oi = ((n*3 + co)*125 + oh)*125 + ow;
            out[oi] = v;
            float d = v - x[oi];
            lsum += d*d;
        }
    }
    #pragma unroll
    for (int off = 16; off; off >>= 1) lsum += __shfl_down_sync(0xffffffffu, lsum, off);
    if ((threadIdx.x & 31) == 0) wsum[threadIdx.x >> 5] = lsum;
    __syncthreads();
    if (threadIdx.x == 0) {
        float s = 0.f;
        #pragma unroll
        for (int i = 0; i < 8; i++) s += wsum[i];
        atomicAdd(&g_recon, (double)s);
    }
}

// ---------------- finalize ----------------
__global__ void k_final(float* __restrict__ out) {
    double mse = g_vq_loss / (65536.0 * 64.0);
    float eq  = (float)(1.25 * mse);
    float rec = (float)g_recon;
    out[0] = eq + rec;
    out[1] = eq;
    out[2] = rec;
}

extern "C" void kernel_launch(void* const* d_in, const int* in_sizes, int n_in,
                              void* d_out, int out_size) {
    const float* x   = (const float*)d_in[0];
    const float* ew1 = (const float*)d_in[1];
    const float* eb1 = (const float*)d_in[2];
    const float* ew2 = (const float*)d_in[3];
    const float* eb2 = (const float*)d_in[4];
    const float* ew3 = (const float*)d_in[5];
    const float* eb3 = (const float*)d_in[6];
    const float* cb  = (const float*)d_in[7];
    const float* dw1 = (const float*)d_in[8];
    const float* db1 = (const float*)d_in[9];
    const float* dw2 = (const float*)d_in[10];
    const float* db2 = (const float*)d_in[11];
    const float* dw3 = (const float*)d_in[12];
    const float* db3 = (const float*)d_in[13];
    float* out = (float*)d_out;

    k_zero <<<1, 1>>>();
    k_conv1<<<1024, 256>>>(x, ew1, eb1);
    k_conv2<<<1024, 256>>>(ew2, eb2);
    k_conv3<<<1024, 256>>>(ew3, eb3);
    k_vq   <<<296, 256>>>(cb);
    k_dec1 <<<1024, 256>>>(dw1, db1);
    k_dec2 <<<2048, 256>>>(dw2, db2);
    k_dec3 <<<3907, 256>>>(dw3, db3, x, out + 3);
    k_final<<<1, 1>>>(out);
}

// round 15
// speedup vs baseline: 1.1072x; 1.1072x over previous
#include <cuda_runtime.h>
#include <cuda_bf16.h>

typedef unsigned long long u64;

// ---------------- f32x2 packed-math helpers (sm_103a FFMA2) ----------------
__device__ __forceinline__ u64 pack2(float lo, float hi) {
    u64 r;
    asm("mov.b64 %0, {%1, %2};" : "=l"(r)
        : "r"(__float_as_uint(lo)), "r"(__float_as_uint(hi)));
    return r;
}
__device__ __forceinline__ u64 bcast2(float v) { return pack2(v, v); }
__device__ __forceinline__ void fma2(u64& d, u64 a, u64 b) {
    asm("fma.rn.f32x2 %0, %1, %2, %0;" : "+l"(d) : "l"(a), "l"(b));
}
__device__ __forceinline__ float2 unpack2(u64 v) {
    unsigned lo, hi;
    asm("mov.b64 {%0, %1}, %2;" : "=r"(lo), "=r"(hi) : "l"(v));
    return make_float2(__uint_as_float(lo), __uint_as_float(hi));
}

// ---------------- scratch (allocation-free: __device__ globals) ----------------
__device__ float g_a1[64*32*63*63];
__device__ float g_a2[64*64*32*32];
__device__ float g_z [64*64*32*32];
__device__ float g_e [64*64*32*32];
__device__ float g_d1[64*64*64*64];
__device__ float g_d2[64*32*128*128];
__device__ double g_vq_loss;
__device__ double g_recon;
__device__ unsigned g_tix;

// ---------------- enc conv1: 3->32, k3 s2 p1, 125->63, relu (R8 form) -------
// block 0 / thread 0 also zeroes the loss accumulators (consumers are later
// graph nodes, so no intra-kernel ordering needed).
__global__ void __launch_bounds__(256) k_conv1(const float* __restrict__ x,
                                               const float* __restrict__ w,
                                               const float* __restrict__ b) {
    if (blockIdx.x == 0 && threadIdx.x == 0) {
        g_vq_loss = 0.0; g_recon = 0.0; g_tix = 0u;
    }
    __shared__ u64 wp[3*9*8];
    int bid  = blockIdx.x;               // 1024 = 64n * 2cog * 8ib
    int ib   = bid & 7;
    int cog  = (bid >> 3) & 1;
    int n    = bid >> 4;
    int co0  = cog * 16;
    for (int i = threadIdx.x; i < 216; i += 256) {
        int jq = i & 7;
        int t  = (i >> 3) % 9;
        int ci = i / 72;
        int co = co0 + 2*jq;
        wp[(ci*9 + t)*8 + jq] = pack2(w[co*27 + ci*9 + t],
                                      w[(co+1)*27 + ci*9 + t]);
    }
    __syncthreads();
    int r2 = ib*256 + threadIdx.x;
    if (r2 >= 2016) return;
    int qp = r2 & 31;
    int oh = r2 >> 5;
    int ow0 = 2*qp;
    bool hasB = (qp != 31);
    u64 accA[8], accB[8];
    #pragma unroll
    for (int jq = 0; jq < 8; jq++) {
        u64 bv = pack2(b[co0+2*jq], b[co0+2*jq+1]);
        accA[jq] = bv; accB[jq] = bv;
    }
    const float* xb = x + n*3*125*125;
    int iwb = 4*qp - 1;
    #pragma unroll
    for (int ci = 0; ci < 3; ci++) {
        u64 col[3][5];
        #pragma unroll
        for (int kh = 0; kh < 3; kh++) {
            int ihh = 2*oh + kh - 1;
            bool hok = (unsigned)ihh < 125u;
            const float* row = xb + (ci*125 + ihh)*125;
            #pragma unroll
            for (int c = 0; c < 5; c++) {
                int iw = iwb + c;
                float v = (hok && (unsigned)iw < 125u) ? row[iw] : 0.f;
                col[kh][c] = bcast2(v);
            }
        }
        #pragma unroll
        for (int kh = 0; kh < 3; kh++) {
            #pragma unroll
            for (int kw = 0; kw < 3; kw++) {
                int t = kh*3 + kw;
                const ulonglong2* Wq = (const ulonglong2*)&wp[(ci*9 + t)*8];
                u64 cA = col[kh][kw];
                u64 cB = col[kh][kw+2];
                #pragma unroll
                for (int h = 0; h < 4; h++) {
                    ulonglong2 W = Wq[h];
                    fma2(accA[2*h],   W.x, cA);
                    fma2(accA[2*h+1], W.y, cA);
                    fma2(accB[2*h],   W.x, cB);
                    fma2(accB[2*h+1], W.y, cB);
                }
            }
        }
    }
    float* ob = g_a1 + ((n*32 + co0)*63 + oh)*63 + ow0;
    #pragma unroll
    for (int jq = 0; jq < 8; jq++) {
        float2 a = unpack2(accA[jq]);
        float2 c = unpack2(accB[jq]);
        float* o0 = ob + (2*jq)*3969;
        float* o1 = o0 + 3969;
        o0[0] = fmaxf(a.x, 0.f);
        o1[0] = fmaxf(a.y, 0.f);
        if (hasB) {
            o0[1] = fmaxf(c.x, 0.f);
            o1[1] = fmaxf(c.y, 0.f);
        }
    }
}

// ---------------- enc conv2: 32->64, k3 s2 p1, 63->32 (R8 form) ------
__global__ void __launch_bounds__(256) k_conv2(const float* __restrict__ w,
                                               const float* __restrict__ b) {
    __shared__ float2 wp[32][4][10];
    int bid   = blockIdx.x;              // 1024 = 64n * 8cog * 2ohhalf
    int ohh   = bid & 1;
    int cog   = (bid >> 1) & 7;
    int n     = bid >> 4;
    int co0   = cog * 8;
    for (int i = threadIdx.x; i < 32*4*9; i += 256) {
        int t  = i % 9;
        int jp = (i/9) & 3;
        int ci = i / 36;
        wp[ci][jp][t] = make_float2(w[((co0 + 2*jp)    *32 + ci)*9 + t],
                                    w[((co0 + 2*jp + 1)*32 + ci)*9 + t]);
    }
    __syncthreads();
    int q  = threadIdx.x & 15;
    int oh = ohh*16 + (threadIdx.x >> 4);
    u64 accA[4], accB[4];
    #pragma unroll
    for (int jp = 0; jp < 4; jp++) {
        u64 bv = pack2(b[co0+2*jp], b[co0+2*jp+1]);
        accA[jp] = bv; accB[jp] = bv;
    }
    const float* ib = g_a1 + n*32*63*63;
    int iwb = 4*q - 1;
    for (int ci = 0; ci < 32; ci++) {
        u64 col[3][5];
        #pragma unroll
        for (int kh = 0; kh < 3; kh++) {
            int ih = 2*oh + kh - 1;
            bool hok = (unsigned)ih < 63u;
            const float* row = ib + (ci*63 + ih)*63;
            #pragma unroll
            for (int c = 0; c < 5; c++) {
                int iw = iwb + c;
                float v = (hok && (unsigned)iw < 63u) ? row[iw] : 0.f;
                col[kh][c] = bcast2(v);
            }
        }
        #pragma unroll
        for (int jp = 0; jp < 4; jp++) {
            const ulonglong2* Wq = (const ulonglong2*)wp[ci][jp];
            ulonglong2 q0 = Wq[0];
            ulonglong2 q1 = Wq[1];
            ulonglong2 q2 = Wq[2];
            ulonglong2 q3 = Wq[3];
            u64 w8 = *(const u64*)&wp[ci][jp][8];
            fma2(accA[jp], q0.x, col[0][0]); fma2(accB[jp], q0.x, col[0][2]);
            fma2(accA[jp], q0.y, col[0][1]); fma2(accB[jp], q0.y, col[0][3]);
            fma2(accA[jp], q1.x, col[0][2]); fma2(accB[jp], q1.x, col[0][4]);
            fma2(accA[jp], q1.y, col[1][0]); fma2(accB[jp], q1.y, col[1][2]);
            fma2(accA[jp], q2.x, col[1][1]); fma2(accB[jp], q2.x, col[1][3]);
            fma2(accA[jp], q2.y, col[1][2]); fma2(accB[jp], q2.y, col[1][4]);
            fma2(accA[jp], q3.x, col[2][0]); fma2(accB[jp], q3.x, col[2][2]);
            fma2(accA[jp], q3.y, col[2][1]); fma2(accB[jp], q3.y, col[2][3]);
            fma2(accA[jp], w8,   col[2][2]); fma2(accB[jp], w8,   col[2][4]);
        }
    }
    int ohw = oh*32 + 2*q;
    #pragma unroll
    for (int jp = 0; jp < 4; jp++) {
        float2 a = unpack2(accA[jp]);
        float2 c = unpack2(accB[jp]);
        *(float2*)&g_a2[(n*64 + co0 + 2*jp    )*1024 + ohw]
            = make_float2(fmaxf(a.x,0.f), fmaxf(c.x,0.f));
        *(float2*)&g_a2[(n*64 + co0 + 2*jp + 1)*1024 + ohw]
            = make_float2(fmaxf(a.y,0.f), fmaxf(c.y,0.f));
    }
}

// ---------------- enc conv3: 64->64 1x1 (R1 scalar form) --------------------
__global__ void k_conv3(const float* __restrict__ w, const float* __restrict__ b) {
    __shared__ float ws[16*64];
    int bid  = blockIdx.x;                 // 1024 = 64n * 4cog * 4tile
    int tile = bid & 3;
    int cog  = (bid >> 2) & 3;
    int n    = bid >> 4;
    int co0  = cog * 16;
    for (int i = threadIdx.x; i < 1024; i += 256) ws[i] = w[co0*64 + i];
    __syncthreads();
    int hw = tile*256 + threadIdx.x;
    float acc[16];
    #pragma unroll
    for (int j = 0; j < 16; j++) acc[j] = b[co0 + j];
    const float* ib = g_a2 + n*64*1024;
    for (int ci = 0; ci < 64; ci++) {
        float v = ib[ci*1024 + hw];
        #pragma unroll
        for (int j = 0; j < 16; j++) acc[j] += ws[j*64 + ci] * v;
    }
    #pragma unroll
    for (int j = 0; j < 16; j++) g_z[(n*64 + co0 + j)*1024 + hw] = acc[j];
}

// ---------------- VQ: EXACT R8 form (zv array + zp packed, 256x256) ---------
__global__ void k_vq(const float* __restrict__ codebook) {
    __shared__ float4 cbs[128][16];
    __shared__ float  cns[128];
    __shared__ float  wsum[8];
    int n  = blockIdx.x * 256 + threadIdx.x;    // exact: 256 blocks
    int bb = n >> 10;
    int hw = n & 1023;
    const float* zb = g_z + bb*65536 + hw;
    float zv[64];
    #pragma unroll
    for (int d = 0; d < 64; d++) zv[d] = zb[d*1024];
    u64 zp[32];
    #pragma unroll
    for (int q = 0; q < 32; q++) zp[q] = pack2(zv[2*q], zv[2*q+1]);
    float best = 3.0e38f; int bidx = 0;
    for (int c = 0; c < 4; c++) {
        __syncthreads();
        const float4* src = (const float4*)(codebook + c*128*64);
        for (int i = threadIdx.x; i < 2048; i += 256)
            ((float4*)cbs)[i] = src[i];
        __syncthreads();
        if (threadIdx.x < 128) {
            const float* cc = (const float*)cbs[threadIdx.x];
            float s = 0.f;
            #pragma unroll
            for (int d = 0; d < 64; d++) s += cc[d]*cc[d];
            cns[threadIdx.x] = s;
        }
        __syncthreads();
        for (int k = 0; k < 128; k += 2) {
            const ulonglong2* ck0 = (const ulonglong2*)cbs[k];
            const ulonglong2* ck1 = (const ulonglong2*)cbs[k+1];
            u64 d0e = 0ull, d0o = 0ull, d1e = 0ull, d1o = 0ull;
            #pragma unroll
            for (int q2 = 0; q2 < 16; q2++) {
                ulonglong2 c0 = ck0[q2];
                ulonglong2 c1 = ck1[q2];
                fma2(d0e, c0.x, zp[2*q2]);
                fma2(d0o, c0.y, zp[2*q2+1]);
                fma2(d1e, c1.x, zp[2*q2]);
                fma2(d1o, c1.y, zp[2*q2+1]);
            }
            float2 a0 = unpack2(d0e), b0 = unpack2(d0o);
            float2 a1 = unpack2(d1e), b1 = unpack2(d1o);
            float dist0 = cns[k]   - 2.f*(a0.x + a0.y + b0.x + b0.y);
            float dist1 = cns[k+1] - 2.f*(a1.x + a1.y + b1.x + b1.y);
            if (dist0 < best) { best = dist0; bidx = c*128 + k; }
            if (dist1 < best) { best = dist1; bidx = c*128 + k + 1; }
        }
    }
    const float* cbest = codebook + bidx*64;
    float* eb = g_e + bb*65536 + hw;
    float ls = 0.f;
    #pragma unroll
    for (int d = 0; d < 64; d++) {
        float qv = cbest[d];
        float df = qv - zv[d];
        ls += df*df;
        eb[d*1024] = qv;
    }
    #pragma unroll
    for (int off = 16; off; off >>= 1) ls += __shfl_down_sync(0xffffffffu, ls, off);
    if ((threadIdx.x & 31) == 0) wsum[threadIdx.x >> 5] = ls;
    __syncthreads();
    if (threadIdx.x == 0) {
        float s = 0.f;
        #pragma unroll
        for (int i = 0; i < 8; i++) s += wsum[i];
        atomicAdd(&g_vq_loss, (double)s);
    }
}

// =====================================================================
// decT core (R8): co-pair lanes, 2 pixels/thread (rows m, m+16),
// LDS.128 weight reads.
// =====================================================================
template<int S>
__device__ __forceinline__ void dec_core(
    const float* __restrict__ ib, const float* __restrict__ w, int CO,
    const float* __restrict__ b, float* __restrict__ ob,
    int co0, int m0, int l0)
{
    __shared__ float2 wp[64][4][10];
    int tid = threadIdx.x;
    for (int i = tid; i < 64*4*9; i += 256) {
        int t  = i % 9;
        int jp = (i/9) & 3;
        int ci = i / 36;
        wp[ci][jp][t] = make_float2(w[(ci*CO + co0 + 2*jp    )*9 + t],
                                    w[(ci*CO + co0 + 2*jp + 1)*9 + t]);
    }
    __syncthreads();

    int dl = tid & 15, dm = tid >> 4;
    int l  = l0 + dl;
    int mA = m0 + dm;
    int mB = mA + 16;
    u64 aA[4][4], aB[4][4];
    #pragma unroll
    for (int jp = 0; jp < 4; jp++) {
        u64 bv = pack2(b[co0+2*jp], b[co0+2*jp+1]);
        #pragma unroll
        for (int p = 0; p < 4; p++) { aA[jp][p] = bv; aB[jp][p] = bv; }
    }
    bool lok  = (l  + 1) < S;
    bool mAok = (mA + 1) < S;
    bool mBok = (mB + 1) < S;
    const float* pA0 = ib + mA*S + l;
    const float* pB0 = ib + mB*S + l;
    for (int ci = 0; ci < 64; ci++) {
        const float* pA = pA0 + ci*S*S;
        const float* pB = pB0 + ci*S*S;
        u64 A00 = bcast2(pA[0]);
        u64 A01 = bcast2(lok ? pA[1] : 0.f);
        u64 A10 = bcast2(mAok ? pA[S] : 0.f);
        u64 A11 = bcast2((mAok && lok) ? pA[S+1] : 0.f);
        u64 B00 = bcast2(pB[0]);
        u64 B01 = bcast2(lok ? pB[1] : 0.f);
        u64 B10 = bcast2(mBok ? pB[S] : 0.f);
        u64 B11 = bcast2((mBok && lok) ? pB[S+1] : 0.f);
        #pragma unroll
        for (int jp = 0; jp < 4; jp++) {
            const ulonglong2* Wq = (const ulonglong2*)wp[ci][jp];
            ulonglong2 q0 = Wq[0];
            ulonglong2 q1 = Wq[1];
            ulonglong2 q2 = Wq[2];
            ulonglong2 q3 = Wq[3];
            u64 w8 = *(const u64*)&wp[ci][jp][8];
            fma2(aA[jp][0], q2.x, A00); fma2(aB[jp][0], q2.x, B00);
            fma2(aA[jp][1], q1.y, A01); fma2(aB[jp][1], q1.y, B01);
            fma2(aA[jp][1], q2.y, A00); fma2(aB[jp][1], q2.y, B00);
            fma2(aA[jp][2], q0.y, A10); fma2(aB[jp][2], q0.y, B10);
            fma2(aA[jp][2], q3.y, A00); fma2(aB[jp][2], q3.y, B00);
            fma2(aA[jp][3], q0.x, A11); fma2(aB[jp][3], q0.x, B11);
            fma2(aA[jp][3], q1.x, A10); fma2(aB[jp][3], q1.x, B10);
            fma2(aA[jp][3], q3.x, A01); fma2(aB[jp][3], q3.x, B01);
            fma2(aA[jp][3], w8,   A00); fma2(aB[jp][3], w8,   B00);
        }
    }
    const int O = 2*S;
    #pragma unroll
    for (int jp = 0; jp < 4; jp++) {
        float2 a0 = unpack2(aA[jp][0]);
        float2 a1 = unpack2(aA[jp][1]);
        float2 a2 = unpack2(aA[jp][2]);
        float2 a3 = unpack2(aA[jp][3]);
        float* o0 = ob + (2*jp)*O*O + (2*mA)*O + 2*l;
        float* o1 = o0 + O*O;
        *(float2*)(o0)     = make_float2(fmaxf(a0.x,0.f), fmaxf(a1.x,0.f));
        *(float2*)(o0 + O) = make_float2(fmaxf(a2.x,0.f), fmaxf(a3.x,0.f));
        *(float2*)(o1)     = make_float2(fmaxf(a0.y,0.f), fmaxf(a1.y,0.f));
        *(float2*)(o1 + O) = make_float2(fmaxf(a2.y,0.f), fmaxf(a3.y,0.f));
        float2 b0 = unpack2(aB[jp][0]);
        float2 b1 = unpack2(aB[jp][1]);
        float2 b2 = unpack2(aB[jp][2]);
        float2 b3 = unpack2(aB[jp][3]);
        float* q0p = ob + (2*jp)*O*O + (2*mB)*O + 2*l;
        float* q1p = q0p + O*O;
        *(float2*)(q0p)     = make_float2(fmaxf(b0.x,0.f), fmaxf(b1.x,0.f));
        *(float2*)(q0p + O) = make_float2(fmaxf(b2.x,0.f), fmaxf(b3.x,0.f));
        *(float2*)(q1p)     = make_float2(fmaxf(b0.y,0.f), fmaxf(b1.y,0.f));
        *(float2*)(q1p + O) = make_float2(fmaxf(b2.y,0.f), fmaxf(b3.y,0.f));
    }
}

// decT1: 64->64, 32x32 -> 64x64
__global__ void __launch_bounds__(256, 2) k_dec1(const float* __restrict__ w,
                                                 const float* __restrict__ b) {
    int bid   = blockIdx.x;            // 1024 = 64n * 8cog * 2lhalf
    int lhalf = bid & 1;
    int cog   = (bid >> 1) & 7;
    int n     = bid >> 4;
    int co0   = cog * 8;
    dec_core<32>(g_e + n*64*1024, w, 64, b, g_d1 + (n*64 + co0)*4096,
                 co0, 0, lhalf*16);
}

// decT2: 64->32, 64x64 -> 128x128
__global__ void __launch_bounds__(256, 2) k_dec2(const float* __restrict__ w,
                                                 const float* __restrict__ b) {
    int bid  = blockIdx.x;             // 2048 = 64n * 4cog * 8tile
    int t    = bid & 7;
    int l0   = (t & 3) * 16;
    int m0   = (t >> 2) * 32;
    int cog  = (bid >> 3) & 3;
    int n    = bid >> 5;
    int co0  = cog * 8;
    dec_core<64>(g_d1 + n*64*4096, w, 32, b, g_d2 + (n*32 + co0)*16384,
                 co0, m0, l0);
}

// ---------------- decT3 (R8) + fused finalize via last-block ticket ---------
__global__ void k_dec3(const float* __restrict__ w, const float* __restrict__ bs,
                       const float* __restrict__ x, float* __restrict__ outbase) {
    __shared__ float ws[384];
    __shared__ float wsum[8];
    float* out = outbase + 3;
    for (int i = threadIdx.x; i < 384; i += 256) ws[i] = w[i];
    __syncthreads();
    int idx = blockIdx.x * 256 + threadIdx.x;
    float lsum = 0.f;
    if (idx < 1000000) {
        int ow = idx % 125; int t = idx / 125;
        int oh = t % 125;   int n = t / 125;
        u64 accA[3], accB[3];
        #pragma unroll
        for (int co = 0; co < 3; co++) { accA[co] = 0ull; accB[co] = 0ull; }
        const float* ib = g_d2 + n*32*16384;
        const float* p  = ib + (oh+1)*128 + (ow+1);
        for (int ci = 0; ci < 32; ci++) {
            const float* q = p + ci*16384;
            u64 A = pack2(q[129], q[128]);
            u64 B = pack2(q[1],   q[0]);
            const ulonglong2* Wq = (const ulonglong2*)(ws + ci*12);
            ulonglong2 v0 = Wq[0];
            ulonglong2 v1 = Wq[1];
            ulonglong2 v2 = Wq[2];
            fma2(accA[0], v0.x, A); fma2(accB[0], v0.y, B);
            fma2(accA[1], v1.x, A); fma2(accB[1], v1.y, B);
            fma2(accA[2], v2.x, A); fma2(accB[2], v2.y, B);
        }
        #pragma unroll
        for (int co = 0; co < 3; co++) {
            float2 a = unpack2(accA[co]);
            float2 c = unpack2(accB[co]);
            float v = bs[co] + a.x + a.y + c.x + c.y;
            int oi = ((n*3 + co)*125 + oh)*125 + ow;
            out[oi] = v;
            float d = v - x[oi];
            lsum += d*d;
        }
    }
    #pragma unroll
    for (int off = 16; off; off >>= 1) lsum += __shfl_down_sync(0xffffffffu, lsum, off);
    if ((threadIdx.x & 31) == 0) wsum[threadIdx.x >> 5] = lsum;
    __syncthreads();
    if (threadIdx.x == 0) {
        float s = 0.f;
        #pragma unroll
        for (int i = 0; i < 8; i++) s += wsum[i];
        atomicAdd(&g_recon, (double)s);
        __threadfence();
        unsigned t = atomicAdd(&g_tix, 1u);
        if (t == 3906u) {                 // last of 3907 blocks
            double mse = g_vq_loss / (65536.0 * 64.0);
            float eq  = (float)(1.25 * mse);
            float rec = (float)g_recon;
            outbase[0] = eq + rec;
            outbase[1] = eq;
            outbase[2] = rec;
        }
    }
}

extern "C" void kernel_launch(void* const* d_in, const int* in_sizes, int n_in,
                              void* d_out, int out_size) {
    const float* x   = (const float*)d_in[0];
    const float* ew1 = (const float*)d_in[1];
    const float* eb1 = (const float*)d_in[2];
    const float* ew2 = (const float*)d_in[3];
    const float* eb2 = (const float*)d_in[4];
    const float* ew3 = (const float*)d_in[5];
    const float* eb3 = (const float*)d_in[6];
    const float* cb  = (const float*)d_in[7];
    const float* dw1 = (const float*)d_in[8];
    const float* db1 = (const float*)d_in[9];
    const float* dw2 = (const float*)d_in[10];
    const float* db2 = (const float*)d_in[11];
    const float* dw3 = (const float*)d_in[12];
    const float* db3 = (const float*)d_in[13];
    float* out = (float*)d_out;

    k_conv1<<<1024, 256>>>(x, ew1, eb1);
    k_conv2<<<1024, 256>>>(ew2, eb2);
    k_conv3<<<1024, 256>>>(ew3, eb3);
    k_vq   <<<256, 256>>>(cb);
    k_dec1 <<<1024, 256>>>(dw1, db1);
    k_dec2 <<<2048, 256>>>(dw2, db2);
    k_dec3 <<<3907, 256>>>(dw3, db3, x, out);
}

// round 16
// speedup vs baseline: 1.1259x; 1.0169x over previous
#include <cuda_runtime.h>
#include <cuda_bf16.h>

typedef unsigned long long u64;

// ---------------- f32x2 packed-math helpers (sm_103a FFMA2) ----------------
__device__ __forceinline__ u64 pack2(float lo, float hi) {
    u64 r;
    asm("mov.b64 %0, {%1, %2};" : "=l"(r)
        : "r"(__float_as_uint(lo)), "r"(__float_as_uint(hi)));
    return r;
}
__device__ __forceinline__ u64 bcast2(float v) { return pack2(v, v); }
__device__ __forceinline__ void fma2(u64& d, u64 a, u64 b) {
    asm("fma.rn.f32x2 %0, %1, %2, %0;" : "+l"(d) : "l"(a), "l"(b));
}
__device__ __forceinline__ float2 unpack2(u64 v) {
    unsigned lo, hi;
    asm("mov.b64 {%0, %1}, %2;" : "=r"(lo), "=r"(hi) : "l"(v));
    return make_float2(__uint_as_float(lo), __uint_as_float(hi));
}

// ---------------- scratch (allocation-free: __device__ globals) ----------------
__device__ float g_a1[64*32*63*63];
__device__ float g_a2[64*64*32*32];
__device__ float g_z [64*64*32*32];
__device__ float g_e [64*64*32*32];
__device__ float g_d1[64*64*64*64];
__device__ float g_d2[64*32*128*128];
__device__ float g_cns[512];
__device__ double g_vq_loss;
__device__ double g_recon;

// k_zero: zero accumulators + precompute codebook norms (1 thread / code)
__global__ void k_zero(const float* __restrict__ cb) {
    int idx = blockIdx.x * 256 + threadIdx.x;
    if (idx == 0) { g_vq_loss = 0.0; g_recon = 0.0; }
    if (idx < 512) {
        const float4* c4 = (const float4*)(cb + idx*64);
        float s = 0.f;
        #pragma unroll
        for (int j = 0; j < 16; j++) {
            float4 v = c4[j];
            s += v.x*v.x; s += v.y*v.y; s += v.z*v.z; s += v.w*v.w;
        }
        g_cns[idx] = s;
    }
}

// ---------------- enc conv1: 3->32, k3 s2 p1, 125->63, relu (R8 form) -------
__global__ void __launch_bounds__(256) k_conv1(const float* __restrict__ x,
                                               const float* __restrict__ w,
                                               const float* __restrict__ b) {
    __shared__ u64 wp[3*9*8];
    int bid  = blockIdx.x;               // 1024 = 64n * 2cog * 8ib
    int ib   = bid & 7;
    int cog  = (bid >> 3) & 1;
    int n    = bid >> 4;
    int co0  = cog * 16;
    for (int i = threadIdx.x; i < 216; i += 256) {
        int jq = i & 7;
        int t  = (i >> 3) % 9;
        int ci = i / 72;
        int co = co0 + 2*jq;
        wp[(ci*9 + t)*8 + jq] = pack2(w[co*27 + ci*9 + t],
                                      w[(co+1)*27 + ci*9 + t]);
    }
    __syncthreads();
    int r2 = ib*256 + threadIdx.x;
    if (r2 >= 2016) return;
    int qp = r2 & 31;
    int oh = r2 >> 5;
    int ow0 = 2*qp;
    bool hasB = (qp != 31);
    u64 accA[8], accB[8];
    #pragma unroll
    for (int jq = 0; jq < 8; jq++) {
        u64 bv = pack2(b[co0+2*jq], b[co0+2*jq+1]);
        accA[jq] = bv; accB[jq] = bv;
    }
    const float* xb = x + n*3*125*125;
    int iwb = 4*qp - 1;
    #pragma unroll
    for (int ci = 0; ci < 3; ci++) {
        u64 col[3][5];
        #pragma unroll
        for (int kh = 0; kh < 3; kh++) {
            int ihh = 2*oh + kh - 1;
            bool hok = (unsigned)ihh < 125u;
            const float* row = xb + (ci*125 + ihh)*125;
            #pragma unroll
            for (int c = 0; c < 5; c++) {
                int iw = iwb + c;
                float v = (hok && (unsigned)iw < 125u) ? row[iw] : 0.f;
                col[kh][c] = bcast2(v);
            }
        }
        #pragma unroll
        for (int kh = 0; kh < 3; kh++) {
            #pragma unroll
            for (int kw = 0; kw < 3; kw++) {
                int t = kh*3 + kw;
                const ulonglong2* Wq = (const ulonglong2*)&wp[(ci*9 + t)*8];
                u64 cA = col[kh][kw];
                u64 cB = col[kh][kw+2];
                #pragma unroll
                for (int h = 0; h < 4; h++) {
                    ulonglong2 W = Wq[h];
                    fma2(accA[2*h],   W.x, cA);
                    fma2(accA[2*h+1], W.y, cA);
                    fma2(accB[2*h],   W.x, cB);
                    fma2(accB[2*h+1], W.y, cB);
                }
            }
        }
    }
    float* ob = g_a1 + ((n*32 + co0)*63 + oh)*63 + ow0;
    #pragma unroll
    for (int jq = 0; jq < 8; jq++) {
        float2 a = unpack2(accA[jq]);
        float2 c = unpack2(accB[jq]);
        float* o0 = ob + (2*jq)*3969;
        float* o1 = o0 + 3969;
        o0[0] = fmaxf(a.x, 0.f);
        o1[0] = fmaxf(a.y, 0.f);
        if (hasB) {
            o0[1] = fmaxf(c.x, 0.f);
            o1[1] = fmaxf(c.y, 0.f);
        }
    }
}

// ---------------- enc conv2: 32->64, k3 s2 p1, 63->32 (R8 form) ------
__global__ void __launch_bounds__(256) k_conv2(const float* __restrict__ w,
                                               const float* __restrict__ b) {
    __shared__ float2 wp[32][4][10];
    int bid   = blockIdx.x;              // 1024 = 64n * 8cog * 2ohhalf
    int ohh   = bid & 1;
    int cog   = (bid >> 1) & 7;
    int n     = bid >> 4;
    int co0   = cog * 8;
    for (int i = threadIdx.x; i < 32*4*9; i += 256) {
        int t  = i % 9;
        int jp = (i/9) & 3;
        int ci = i / 36;
        wp[ci][jp][t] = make_float2(w[((co0 + 2*jp)    *32 + ci)*9 + t],
                                    w[((co0 + 2*jp + 1)*32 + ci)*9 + t]);
    }
    __syncthreads();
    int q  = threadIdx.x & 15;
    int oh = ohh*16 + (threadIdx.x >> 4);
    u64 accA[4], accB[4];
    #pragma unroll
    for (int jp = 0; jp < 4; jp++) {
        u64 bv = pack2(b[co0+2*jp], b[co0+2*jp+1]);
        accA[jp] = bv; accB[jp] = bv;
    }
    const float* ib = g_a1 + n*32*63*63;
    int iwb = 4*q - 1;
    for (int ci = 0; ci < 32; ci++) {
        u64 col[3][5];
        #pragma unroll
        for (int kh = 0; kh < 3; kh++) {
            int ih = 2*oh + kh - 1;
            bool hok = (unsigned)ih < 63u;
            const float* row = ib + (ci*63 + ih)*63;
            #pragma unroll
            for (int c = 0; c < 5; c++) {
                int iw = iwb + c;
                float v = (hok && (unsigned)iw < 63u) ? row[iw] : 0.f;
                col[kh][c] = bcast2(v);
            }
        }
        #pragma unroll
        for (int jp = 0; jp < 4; jp++) {
            const ulonglong2* Wq = (const ulonglong2*)wp[ci][jp];
            ulonglong2 q0 = Wq[0];
            ulonglong2 q1 = Wq[1];
            ulonglong2 q2 = Wq[2];
            ulonglong2 q3 = Wq[3];
            u64 w8 = *(const u64*)&wp[ci][jp][8];
            fma2(accA[jp], q0.x, col[0][0]); fma2(accB[jp], q0.x, col[0][2]);
            fma2(accA[jp], q0.y, col[0][1]); fma2(accB[jp], q0.y, col[0][3]);
            fma2(accA[jp], q1.x, col[0][2]); fma2(accB[jp], q1.x, col[0][4]);
            fma2(accA[jp], q1.y, col[1][0]); fma2(accB[jp], q1.y, col[1][2]);
            fma2(accA[jp], q2.x, col[1][1]); fma2(accB[jp], q2.x, col[1][3]);
            fma2(accA[jp], q2.y, col[1][2]); fma2(accB[jp], q2.y, col[1][4]);
            fma2(accA[jp], q3.x, col[2][0]); fma2(accB[jp], q3.x, col[2][2]);
            fma2(accA[jp], q3.y, col[2][1]); fma2(accB[jp], q3.y, col[2][3]);
            fma2(accA[jp], w8,   col[2][2]); fma2(accB[jp], w8,   col[2][4]);
        }
    }
    int ohw = oh*32 + 2*q;
    #pragma unroll
    for (int jp = 0; jp < 4; jp++) {
        float2 a = unpack2(accA[jp]);
        float2 c = unpack2(accB[jp]);
        *(float2*)&g_a2[(n*64 + co0 + 2*jp    )*1024 + ohw]
            = make_float2(fmaxf(a.x,0.f), fmaxf(c.x,0.f));
        *(float2*)&g_a2[(n*64 + co0 + 2*jp + 1)*1024 + ohw]
            = make_float2(fmaxf(a.y,0.f), fmaxf(c.y,0.f));
    }
}

// ---------------- enc conv3: 64->64 1x1 (R1 scalar form) --------------------
__global__ void k_conv3(const float* __restrict__ w, const float* __restrict__ b) {
    __shared__ float ws[16*64];
    int bid  = blockIdx.x;                 // 1024 = 64n * 4cog * 4tile
    int tile = bid & 3;
    int cog  = (bid >> 2) & 3;
    int n    = bid >> 4;
    int co0  = cog * 16;
    for (int i = threadIdx.x; i < 1024; i += 256) ws[i] = w[co0*64 + i];
    __syncthreads();
    int hw = tile*256 + threadIdx.x;
    float acc[16];
    #pragma unroll
    for (int j = 0; j < 16; j++) acc[j] = b[co0 + j];
    const float* ib = g_a2 + n*64*1024;
    for (int ci = 0; ci < 64; ci++) {
        float v = ib[ci*1024 + hw];
        #pragma unroll
        for (int j = 0; j < 16; j++) acc[j] += ws[j*64 + ci] * v;
    }
    #pragma unroll
    for (int j = 0; j < 16; j++) g_z[(n*64 + co0 + j)*1024 + hw] = acc[j];
}

// ---------------- VQ: R8 hot loop; norms from g_cns; float4 gather epilogue --
__global__ void k_vq(const float* __restrict__ codebook) {
    __shared__ float4 cbs[128][16];
    __shared__ float  wsum[8];
    int n  = blockIdx.x * 256 + threadIdx.x;    // exact: 256 blocks
    int bb = n >> 10;
    int hw = n & 1023;
    const float* zb = g_z + bb*65536 + hw;
    u64 zp[32];
    #pragma unroll
    for (int q = 0; q < 32; q++)
        zp[q] = pack2(zb[(2*q)*1024], zb[(2*q+1)*1024]);
    float best = 3.0e38f; int bidx = 0;
    for (int c = 0; c < 4; c++) {
        __syncthreads();
        const float4* src = (const float4*)(codebook + c*128*64);
        for (int i = threadIdx.x; i < 2048; i += 256)
            ((float4*)cbs)[i] = src[i];
        __syncthreads();
        const float* cnp = g_cns + c*128;
        for (int k = 0; k < 128; k += 2) {
            const ulonglong2* ck0 = (const ulonglong2*)cbs[k];
            const ulonglong2* ck1 = (const ulonglong2*)cbs[k+1];
            u64 d0e = 0ull, d0o = 0ull, d1e = 0ull, d1o = 0ull;
            #pragma unroll
            for (int q2 = 0; q2 < 16; q2++) {
                ulonglong2 c0 = ck0[q2];
                ulonglong2 c1 = ck1[q2];
                fma2(d0e, c0.x, zp[2*q2]);
                fma2(d0o, c0.y, zp[2*q2+1]);
                fma2(d1e, c1.x, zp[2*q2]);
                fma2(d1o, c1.y, zp[2*q2+1]);
            }
            float2 a0 = unpack2(d0e), b0 = unpack2(d0o);
            float2 a1 = unpack2(d1e), b1 = unpack2(d1o);
            float dist0 = cnp[k]   - 2.f*(a0.x + a0.y + b0.x + b0.y);
            float dist1 = cnp[k+1] - 2.f*(a1.x + a1.y + b1.x + b1.y);
            if (dist0 < best) { best = dist0; bidx = c*128 + k; }
            if (dist1 < best) { best = dist1; bidx = c*128 + k + 1; }
        }
    }
    // epilogue: float4 gather of winning code, loss in ascending-d order
    const float4* cb4 = (const float4*)(codebook + bidx*64);
    float* eb = g_e + bb*65536 + hw;
    float ls = 0.f;
    #pragma unroll
    for (int j = 0; j < 16; j++) {
        float4 qv = cb4[j];
        float2 zlo = unpack2(zp[2*j]);      // z[4j],   z[4j+1]
        float2 zhi = unpack2(zp[2*j + 1]);  // z[4j+2], z[4j+3]
        float d0 = qv.x - zlo.x; ls += d0*d0;
        float d1 = qv.y - zlo.y; ls += d1*d1;
        float d2 = qv.z - zhi.x; ls += d2*d2;
        float d3 = qv.w - zhi.y; ls += d3*d3;
        eb[(4*j    )*1024] = qv.x;
        eb[(4*j + 1)*1024] = qv.y;
        eb[(4*j + 2)*1024] = qv.z;
        eb[(4*j + 3)*1024] = qv.w;
    }
    #pragma unroll
    for (int off = 16; off; off >>= 1) ls += __shfl_down_sync(0xffffffffu, ls, off);
    if ((threadIdx.x & 31) == 0) wsum[threadIdx.x >> 5] = ls;
    __syncthreads();
    if (threadIdx.x == 0) {
        float s = 0.f;
        #pragma unroll
        for (int i = 0; i < 8; i++) s += wsum[i];
        atomicAdd(&g_vq_loss, (double)s);
    }
}

// =====================================================================
// decT core (R8): co-pair lanes, 2 pixels/thread (rows m, m+16),
// LDS.128 weight reads.
// =====================================================================
template<int S>
__device__ __forceinline__ void dec_core(
    const float* __restrict__ ib, const float* __restrict__ w, int CO,
    const float* __restrict__ b, float* __restrict__ ob,
    int co0, int m0, int l0)
{
    __shared__ float2 wp[64][4][10];
    int tid = threadIdx.x;
    for (int i = tid; i < 64*4*9; i += 256) {
        int t  = i % 9;
        int jp = (i/9) & 3;
        int ci = i / 36;
        wp[ci][jp][t] = make_float2(w[(ci*CO + co0 + 2*jp    )*9 + t],
                                    w[(ci*CO + co0 + 2*jp + 1)*9 + t]);
    }
    __syncthreads();

    int dl = tid & 15, dm = tid >> 4;
    int l  = l0 + dl;
    int mA = m0 + dm;
    int mB = mA + 16;
    u64 aA[4][4], aB[4][4];
    #pragma unroll
    for (int jp = 0; jp < 4; jp++) {
        u64 bv = pack2(b[co0+2*jp], b[co0+2*jp+1]);
        #pragma unroll
        for (int p = 0; p < 4; p++) { aA[jp][p] = bv; aB[jp][p] = bv; }
    }
    bool lok  = (l  + 1) < S;
    bool mAok = (mA + 1) < S;
    bool mBok = (mB + 1) < S;
    const float* pA0 = ib + mA*S + l;
    const float* pB0 = ib + mB*S + l;
    for (int ci = 0; ci < 64; ci++) {
        const float* pA = pA0 + ci*S*S;
        const float* pB = pB0 + ci*S*S;
        u64 A00 = bcast2(pA[0]);
        u64 A01 = bcast2(lok ? pA[1] : 0.f);
        u64 A10 = bcast2(mAok ? pA[S] : 0.f);
        u64 A11 = bcast2((mAok && lok) ? pA[S+1] : 0.f);
        u64 B00 = bcast2(pB[0]);
        u64 B01 = bcast2(lok ? pB[1] : 0.f);
        u64 B10 = bcast2(mBok ? pB[S] : 0.f);
        u64 B11 = bcast2((mBok && lok) ? pB[S+1] : 0.f);
        #pragma unroll
        for (int jp = 0; jp < 4; jp++) {
            const ulonglong2* Wq = (const ulonglong2*)wp[ci][jp];
            ulonglong2 q0 = Wq[0];
            ulonglong2 q1 = Wq[1];
            ulonglong2 q2 = Wq[2];
            ulonglong2 q3 = Wq[3];
            u64 w8 = *(const u64*)&wp[ci][jp][8];
            fma2(aA[jp][0], q2.x, A00); fma2(aB[jp][0], q2.x, B00);
            fma2(aA[jp][1], q1.y, A01); fma2(aB[jp][1], q1.y, B01);
            fma2(aA[jp][1], q2.y, A00); fma2(aB[jp][1], q2.y, B00);
            fma2(aA[jp][2], q0.y, A10); fma2(aB[jp][2], q0.y, B10);
            fma2(aA[jp][2], q3.y, A00); fma2(aB[jp][2], q3.y, B00);
            fma2(aA[jp][3], q0.x, A11); fma2(aB[jp][3], q0.x, B11);
            fma2(aA[jp][3], q1.x, A10); fma2(aB[jp][3], q1.x, B10);
            fma2(aA[jp][3], q3.x, A01); fma2(aB[jp][3], q3.x, B01);
            fma2(aA[jp][3], w8,   A00); fma2(aB[jp][3], w8,   B00);
        }
    }
    const int O = 2*S;
    #pragma unroll
    for (int jp = 0; jp < 4; jp++) {
        float2 a0 = unpack2(aA[jp][0]);
        float2 a1 = unpack2(aA[jp][1]);
        float2 a2 = unpack2(aA[jp][2]);
        float2 a3 = unpack2(aA[jp][3]);
        float* o0 = ob + (2*jp)*O*O + (2*mA)*O + 2*l;
        float* o1 = o0 + O*O;
        *(float2*)(o0)     = make_float2(fmaxf(a0.x,0.f), fmaxf(a1.x,0.f));
        *(float2*)(o0 + O) = make_float2(fmaxf(a2.x,0.f), fmaxf(a3.x,0.f));
        *(float2*)(o1)     = make_float2(fmaxf(a0.y,0.f), fmaxf(a1.y,0.f));
        *(float2*)(o1 + O) = make_float2(fmaxf(a2.y,0.f), fmaxf(a3.y,0.f));
        float2 b0 = unpack2(aB[jp][0]);
        float2 b1 = unpack2(aB[jp][1]);
        float2 b2 = unpack2(aB[jp][2]);
        float2 b3 = unpack2(aB[jp][3]);
        float* q0p = ob + (2*jp)*O*O + (2*mB)*O + 2*l;
        float* q1p = q0p + O*O;
        *(float2*)(q0p)     = make_float2(fmaxf(b0.x,0.f), fmaxf(b1.x,0.f));
        *(float2*)(q0p + O) = make_float2(fmaxf(b2.x,0.f), fmaxf(b3.x,0.f));
        *(float2*)(q1p)     = make_float2(fmaxf(b0.y,0.f), fmaxf(b1.y,0.f));
        *(float2*)(q1p + O) = make_float2(fmaxf(b2.y,0.f), fmaxf(b3.y,0.f));
    }
}

// decT1: 64->64, 32x32 -> 64x64
__global__ void __launch_bounds__(256, 2) k_dec1(const float* __restrict__ w,
                                                 const float* __restrict__ b) {
    int bid   = blockIdx.x;            // 1024 = 64n * 8cog * 2lhalf
    int lhalf = bid & 1;
    int cog   = (bid >> 1) & 7;
    int n     = bid >> 4;
    int co0   = cog * 8;
    dec_core<32>(g_e + n*64*1024, w, 64, b, g_d1 + (n*64 + co0)*4096,
                 co0, 0, lhalf*16);
}

// decT2: 64->32, 64x64 -> 128x128
__global__ void __launch_bounds__(256, 2) k_dec2(const float* __restrict__ w,
                                                 const float* __restrict__ b) {
    int bid  = blockIdx.x;             // 2048 = 64n * 4cog * 8tile
    int t    = bid & 7;
    int l0   = (t & 3) * 16;
    int m0   = (t >> 2) * 32;
    int cog  = (bid >> 3) & 3;
    int n    = bid >> 5;
    int co0  = cog * 8;
    dec_core<64>(g_d1 + n*64*4096, w, 32, b, g_d2 + (n*32 + co0)*16384,
                 co0, m0, l0);
}

// ---------------- decT3: 32->3, k2 s1 p2, 128->125 + recon loss (R8) --------
__global__ void k_dec3(const float* __restrict__ w, const float* __restrict__ bs,
                       const float* __restrict__ x, float* __restrict__ out) {
    __shared__ float ws[384];
    __shared__ float wsum[8];
    for (int i = threadIdx.x; i < 384; i += 256) ws[i] = w[i];
    __syncthreads();
    int idx = blockIdx.x * 256 + threadIdx.x;
    float lsum = 0.f;
    if (idx < 1000000) {
        int ow = idx % 125; int t = idx / 125;
        int oh = t % 125;   int n = t / 125;
        u64 accA[3], accB[3];
        #pragma unroll
        for (int co = 0; co < 3; co++) { accA[co] = 0ull; accB[co] = 0ull; }
        const float* ib = g_d2 + n*32*16384;
        const float* p  = ib + (oh+1)*128 + (ow+1);
        for (int ci = 0; ci < 32; ci++) {
            const float* q = p + ci*16384;
            u64 A = pack2(q[129], q[128]);
            u64 B = pack2(q[1],   q[0]);
            const ulonglong2* Wq = (const ulonglong2*)(ws + ci*12);
            ulonglong2 v0 = Wq[0];
            ulonglong2 v1 = Wq[1];
            ulonglong2 v2 = Wq[2];
            fma2(accA[0], v0.x, A); fma2(accB[0], v0.y, B);
            fma2(accA[1], v1.x, A); fma2(accB[1], v1.y, B);
            fma2(accA[2], v2.x, A); fma2(accB[2], v2.y, B);
        }
        #pragma unroll
        for (int co = 0; co < 3; co++) {
            float2 a = unpack2(accA[co]);
            float2 c = unpack2(accB[co]);
            float v = bs[co] + a.x + a.y + c.x + c.y;
            int oi = ((n*3 + co)*125 + oh)*125 + ow;
            out[oi] = v;
            float d = v - x[oi];
            lsum += d*d;
        }
    }
    #pragma unroll
    for (int off = 16; off; off >>= 1) lsum += __shfl_down_sync(0xffffffffu, lsum, off);
    if ((threadIdx.x & 31) == 0) wsum[threadIdx.x >> 5] = lsum;
    __syncthreads();
    if (threadIdx.x == 0) {
        float s = 0.f;
        #pragma unroll
        for (int i = 0; i < 8; i++) s += wsum[i];
        atomicAdd(&g_recon, (double)s);
    }
}

// ---------------- finalize ----------------
__global__ void k_final(float* __restrict__ out) {
    double mse = g_vq_loss / (65536.0 * 64.0);
    float eq  = (float)(1.25 * mse);
    float rec = (float)g_recon;
    out[0] = eq + rec;
    out[1] = eq;
    out[2] = rec;
}

extern "C" void kernel_launch(void* const* d_in, const int* in_sizes, int n_in,
                              void* d_out, int out_size) {
    const float* x   = (const float*)d_in[0];
    const float* ew1 = (const float*)d_in[1];
    const float* eb1 = (const float*)d_in[2];
    const float* ew2 = (const float*)d_in[3];
    const float* eb2 = (const float*)d_in[4];
    const float* ew3 = (const float*)d_in[5];
    const float* eb3 = (const float*)d_in[6];
    const float* cb  = (const float*)d_in[7];
    const float* dw1 = (const float*)d_in[8];
    const float* db1 = (const float*)d_in[9];
    const float* dw2 = (const float*)d_in[10];
    const float* db2 = (const float*)d_in[11];
    const float* dw3 = (const float*)d_in[12];
    const float* db3 = (const float*)d_in[13];
    float* out = (float*)d_out;

    k_zero <<<2, 256>>>(cb);
    k_conv1<<<1024, 256>>>(x, ew1, eb1);
    k_conv2<<<1024, 256>>>(ew2, eb2);
    k_conv3<<<1024, 256>>>(ew3, eb3);
    k_vq   <<<256, 256>>>(cb);
    k_dec1 <<<1024, 256>>>(dw1, db1);
    k_dec2 <<<2048, 256>>>(dw2, db2);
    k_dec3 <<<3907, 256>>>(dw3, db3, x, out + 3);
    k_final<<<1, 1>>>(out);
}